// round 15
// baseline (speedup 1.0000x reference)
#include <cuda_runtime.h>
#include <cuda_fp16.h>
#include <cstdint>

// LocalAtomAttention (round 14): register-resident Q/K attention (r13 fixed).
// Warp tile = (32 tokens x 1 head): Q/K GEMM accumulators repack in-register
// to mma A/B fragments; softmax in registers; V via warp-private XH round trip
// (ldsm.trans + __syncwarp). smem = X/V tile + Y tile + 2 correctly-sized W
// buffers (34816B each!) = 104960B/CTA, 2 CTAs/SM. 4 block barriers.

namespace laa {
constexpr int C = 128, TOKS = 64, NT = 256;
constexpr uint32_t RS = 272;            // smem row stride bytes
constexpr uint32_t XH = 0,              // X then V tile   (64 rows, 17408B)
                   YT = 17408,          // Y tile          (64 rows, 17408B)
                   WA = 34816,          // W buffer A      (128 rows, 34816B)
                   WB = 69632,          // W buffer B      (128 rows, 34816B)
                   MSK = 104448, RM = 104704, TOTAL = 104960;  // x2 <= 228KB
constexpr float SCALE = 0.17677669529663687f;  // 1/sqrt(32)
}

// Prepped fp16 weights: [4] = {Wq*s, Wk, Wv, Wo}, 272B rows, 34816B each.
__device__ __align__(16) unsigned char g_wimg[4][34816];
__device__ float g_bias[4][128];   // {bq*s, bk, bv, bo}

// ---------------- helpers ----------------
__device__ __forceinline__ uint32_t smem_u32(const void* p) {
    uint32_t a;
    asm("{ .reg .u64 t; cvta.to.shared.u64 t, %1; cvt.u32.u64 %0, t; }" : "=r"(a) : "l"(p));
    return a;
}
__device__ __forceinline__ uint32_t pkh(float a, float b) {
    __half2 h = __floats2half2_rn(a, b);
    return *(uint32_t*)&h;
}
__device__ __forceinline__ void ldsm4(uint32_t& a0, uint32_t& a1, uint32_t& a2,
                                      uint32_t& a3, uint32_t addr) {
    asm volatile("ldmatrix.sync.aligned.m8n8.x4.shared.b16 {%0,%1,%2,%3}, [%4];"
                 : "=r"(a0), "=r"(a1), "=r"(a2), "=r"(a3) : "r"(addr));
}
__device__ __forceinline__ void ldsm4t(uint32_t& a0, uint32_t& a1, uint32_t& a2,
                                       uint32_t& a3, uint32_t addr) {
    asm volatile("ldmatrix.sync.aligned.m8n8.x4.trans.shared.b16 {%0,%1,%2,%3}, [%4];"
                 : "=r"(a0), "=r"(a1), "=r"(a2), "=r"(a3) : "r"(addr));
}
__device__ __forceinline__ void mma16816(float d[4], uint32_t a0, uint32_t a1,
                                         uint32_t a2, uint32_t a3,
                                         uint32_t b0, uint32_t b1) {
    asm volatile(
        "mma.sync.aligned.m16n8k16.row.col.f32.f16.f16.f32 "
        "{%0,%1,%2,%3}, {%4,%5,%6,%7}, {%8,%9}, {%0,%1,%2,%3};"
        : "+f"(d[0]), "+f"(d[1]), "+f"(d[2]), "+f"(d[3])
        : "r"(a0), "r"(a1), "r"(a2), "r"(a3), "r"(b0), "r"(b1));
}
__device__ __forceinline__ void cpa16(uint32_t dst, const unsigned char* src) {
    uint64_t g;
    asm("cvta.to.global.u64 %0, %1;" : "=l"(g) : "l"(src));
    asm volatile("cp.async.cg.shared.global [%0], [%1], 16;" :: "r"(dst), "l"(g));
}
#define CPA_COMMIT() asm volatile("cp.async.commit_group;" ::: "memory")
#define CPA_WAIT0()  asm volatile("cp.async.wait_group 0;" ::: "memory")
#define CPA_WAIT1()  asm volatile("cp.async.wait_group 1;" ::: "memory")

// ---------------- prep kernel (32 blocks: 4 matrices x 8 chunks) ----------------
__global__ void prep_split(const float* __restrict__ Wq, const float* __restrict__ bq,
                           const float* __restrict__ Wk, const float* __restrict__ bk,
                           const float* __restrict__ Wv, const float* __restrict__ bv,
                           const float* __restrict__ Wo, const float* __restrict__ bo) {
    const int m = blockIdx.x >> 3;
    const int chunk = blockIdx.x & 7;
    const float* src  = (m == 0) ? Wq : (m == 1) ? Wk : (m == 2) ? Wv : Wo;
    const float* bsrc = (m == 0) ? bq : (m == 1) ? bk : (m == 2) ? bv : bo;
    const float sc = (m == 0) ? laa::SCALE : 1.f;
    unsigned char* img = g_wimg[m];
    for (int i = chunk * 2048 + threadIdx.x; i < (chunk + 1) * 2048; i += blockDim.x) {
        int row = i >> 7, col = i & 127;
        *(__half*)(img + row * laa::RS + col * 2) = __float2half_rn(src[i] * sc);
    }
    if (chunk == 0 && threadIdx.x < 128)
        g_bias[m][threadIdx.x] = bsrc[threadIdx.x] * sc;
}

// ---------------- main kernel ----------------
using namespace laa;

// Load A fragments for a 32-row warp tile over K=128: 16 ldsm4 -> 64 regs.
__device__ __forceinline__ void load_a(uint32_t a_t, int r0, int lane, uint32_t* af) {
    const uint32_t aoff = (uint32_t)(r0 + (lane & 15)) * RS + ((lane >> 4) << 4);
#pragma unroll
    for (int ks = 0; ks < 8; ++ks) {
        ldsm4(af[ks*8+0], af[ks*8+1], af[ks*8+2], af[ks*8+3], a_t + aoff + ks * 32);
        ldsm4(af[ks*8+4], af[ks*8+5], af[ks*8+6], af[ks*8+7], a_t + aoff + 16 * RS + ks * 32);
    }
}

// Warp GEMM with cached A: D[32x32] += A·B^T, B fragments via ldsm from smem.
__device__ __forceinline__ void warp_gemm_c(const uint32_t* af, uint32_t wbuf,
                                            int nc0, float d[2][4][4], int lane) {
    const uint32_t brow = (lane & 7) + ((lane & 16) >> 1);
    const uint32_t bkof = (lane & 8) << 1;
#pragma unroll
    for (int ks = 0; ks < 8; ++ks) {
        const uint32_t kb = ks * 32;
        const uint32_t* a = af + ks * 8;
#pragma unroll
        for (int np = 0; np < 2; ++np) {
            const uint32_t ba = (uint32_t)(nc0 + np * 16 + brow) * RS + bkof + kb;
            uint32_t b0, b1, b2, b3;
            ldsm4(b0, b1, b2, b3, wbuf + ba);
            mma16816(d[0][2 * np],     a[0], a[1], a[2], a[3], b0, b1);
            mma16816(d[0][2 * np + 1], a[0], a[1], a[2], a[3], b2, b3);
            mma16816(d[1][2 * np],     a[4], a[5], a[6], a[7], b0, b1);
            mma16816(d[1][2 * np + 1], a[4], a[5], a[6], a[7], b2, b3);
        }
    }
}

// Stage full W matrix m (34816 B) into dst via cp.async; commits one group.
__device__ __forceinline__ void stage_w(uint32_t dst, int m, int tid) {
    const unsigned char* src = g_wimg[m];
#pragma unroll 2
    for (int i = tid; i < 2176; i += NT) cpa16(dst + i * 16, src + i * 16);
    CPA_COMMIT();
}

__global__ __launch_bounds__(NT, 2)
void laa_mma_kernel(const float* __restrict__ x, const int* __restrict__ mask,
                    float* __restrict__ out)
{
    extern __shared__ __align__(16) char sm[];
    const uint32_t sb = smem_u32(sm);
    const int tid = threadIdx.x, lane = tid & 31, w = tid >> 5;
    const long long tok0 = (long long)blockIdx.x * TOKS;

    float* msk_f = (float*)(sm + MSK);
    float* rm_f  = (float*)(sm + RM);

    // ---- P0: stage Wq->WA, Wk->WB; X load + fp16 convert; masks ----
    stage_w(sb + WA, 0, tid);
    stage_w(sb + WB, 1, tid);
#pragma unroll
    for (int it = 0; it < 8; ++it) {
        int idx = it * NT + tid;              // float4 index over [64][32]
        int row = idx >> 5, c4 = idx & 31;
        float4 v = __ldg((const float4*)x + (tok0 + row) * 32 + c4);
        uint2 hv;
        hv.x = pkh(v.x, v.y); hv.y = pkh(v.z, v.w);
        *(uint2*)(sm + XH + row * RS + c4 * 8) = hv;
    }
    if (tid < TOKS) {
        msk_f[tid] = (__ldg(&mask[tok0 + tid]) != 0) ? 1.f : 0.f;
        long long b = tok0 + (tid & ~3);
        int any = __ldg(&mask[b]) | __ldg(&mask[b + 1]) | __ldg(&mask[b + 2]) | __ldg(&mask[b + 3]);
        rm_f[tid] = (any != 0) ? 1.f : 0.f;
    }
    CPA_WAIT0();
    __syncthreads();                          // (1) X, Wq, Wk, masks visible

    const int r0 = (w >> 2) * 32;             // {0,32}  token rows
    const int nc0 = (w & 3) * 32;             // {0,32,64,96}  = head*32
    const int rq = lane >> 2;
    const int c2 = 2 * (lane & 3);

    // ---- cache X A-fragments (used by Q, K, V GEMMs) ----
    uint32_t af[64];
    load_a(sb + XH, r0, lane, af);

    // bias column offsets for this warp's 4 n-tiles
    int colj[4];
#pragma unroll
    for (int j = 0; j < 4; ++j) colj[j] = nc0 + (j >> 1) * 16 + (j & 1) * 8 + c2;

    // ---- Q GEMM (WA) -> A-fragments (in registers) ----
    uint32_t qa[2][8];
    {
        float d[2][4][4] = {};
        warp_gemm_c(af, sb + WA, nc0, d, lane);
#pragma unroll
        for (int mi = 0; mi < 2; ++mi)
#pragma unroll
            for (int g = 0; g < 2; ++g) {
                const int j0 = 2 * g, j1 = 2 * g + 1;
                const float b00 = g_bias[0][colj[j0]], b01 = g_bias[0][colj[j0] + 1];
                const float b10 = g_bias[0][colj[j1]], b11 = g_bias[0][colj[j1] + 1];
                qa[mi][g*4+0] = pkh(d[mi][j0][0] + b00, d[mi][j0][1] + b01);
                qa[mi][g*4+1] = pkh(d[mi][j0][2] + b00, d[mi][j0][3] + b01);
                qa[mi][g*4+2] = pkh(d[mi][j1][0] + b10, d[mi][j1][1] + b11);
                qa[mi][g*4+3] = pkh(d[mi][j1][2] + b10, d[mi][j1][3] + b11);
            }
    }
    __syncthreads();                          // (2) all WA (Wq) reads done

    // ---- stage Wv->WA (group; hidden behind K GEMM + softmax) ----
    stage_w(sb + WA, 2, tid);

    // ---- K GEMM (WB) -> B-fragments (in registers) ----
    uint32_t kb[2][8];
    {
        float d[2][4][4] = {};
        warp_gemm_c(af, sb + WB, nc0, d, lane);
#pragma unroll
        for (int mi = 0; mi < 2; ++mi) {
#pragma unroll
            for (int j = 0; j < 4; ++j) {
                const float b0 = g_bias[1][colj[j]], b1 = g_bias[1][colj[j] + 1];
                kb[mi][j]     = pkh(d[mi][j][0] + b0, d[mi][j][1] + b1);
                kb[mi][j + 4] = pkh(d[mi][j][2] + b0, d[mi][j][3] + b1);
            }
        }
    }

    // ---- S = Q·K^T (diagonal tiles) + masked softmax -> P fragments ----
    uint32_t pa[2][2];
    const int valid = (((lane >> 4) & 1) == ((lane >> 1) & 1));
#pragma unroll
    for (int mi = 0; mi < 2; ++mi) {
        float sn0[4] = {}, sn1[4] = {};
        mma16816(sn0, qa[mi][0], qa[mi][1], qa[mi][2], qa[mi][3], kb[mi][0], kb[mi][1]);
        mma16816(sn0, qa[mi][4], qa[mi][5], qa[mi][6], qa[mi][7], kb[mi][2], kb[mi][3]);
        mma16816(sn1, qa[mi][0], qa[mi][1], qa[mi][2], qa[mi][3], kb[mi][4], kb[mi][5]);
        mma16816(sn1, qa[mi][4], qa[mi][5], qa[mi][6], qa[mi][7], kb[mi][6], kb[mi][7]);

        const int mb = r0 + mi * 16;
        const float mk0a = msk_f[mb + c2],     mk0b = msk_f[mb + c2 + 1];
        const float mk1a = msk_f[mb + 8 + c2], mk1b = msk_f[mb + 8 + c2 + 1];
        float s0 = (mk0a != 0.f) ? sn0[0] : -1e30f;
        float s1 = (mk0b != 0.f) ? sn0[1] : -1e30f;
        float u0 = (mk1a != 0.f) ? sn1[2] : -1e30f;
        float u1 = (mk1b != 0.f) ? sn1[3] : -1e30f;
        float rm0 = fmaxf(s0, s1), rm1 = fmaxf(u0, u1);
        rm0 = fmaxf(rm0, __shfl_xor_sync(0xffffffffu, rm0, 1));
        rm1 = fmaxf(rm1, __shfl_xor_sync(0xffffffffu, rm1, 1));
        float e0 = __expf(s0 - rm0), e1 = __expf(s1 - rm0);
        float f0 = __expf(u0 - rm1), f1 = __expf(u1 - rm1);
        float su0 = e0 + e1, su1 = f0 + f1;
        su0 += __shfl_xor_sync(0xffffffffu, su0, 1);
        su1 += __shfl_xor_sync(0xffffffffu, su1, 1);
        pa[mi][0] = 0u; pa[mi][1] = 0u;
        if (valid) {
            const float i0 = 1.f / su0, i1 = 1.f / su1;
            pa[mi][0] = pkh(e0 * i0, e1 * i0);
            pa[mi][1] = pkh(f0 * i1, f1 * i1);
        }
    }
    __syncthreads();                          // (3) all WB (Wk) reads done

    // ---- stage Wo->WB (hidden behind V GEMM + P·V); wait Wv only ----
    stage_w(sb + WB, 3, tid);
    CPA_WAIT1();                              // Wv (older group) complete
    __syncthreads();                          // (4) Wv visible to all warps

    // ---- V GEMM (WA); write V (fp16, +bias) into warp-private XH block ----
    {
        float d[2][4][4] = {};
        warp_gemm_c(af, sb + WA, nc0, d, lane);
#pragma unroll
        for (int mi = 0; mi < 2; ++mi) {
            const int ra = r0 + mi * 16 + rq, rb = ra + 8;
#pragma unroll
            for (int j = 0; j < 4; ++j) {
                const float b0 = g_bias[2][colj[j]], b1 = g_bias[2][colj[j] + 1];
                *(uint32_t*)(sm + XH + ra * RS + colj[j] * 2) =
                    pkh(d[mi][j][0] + b0, d[mi][j][1] + b1);
                *(uint32_t*)(sm + XH + rb * RS + colj[j] * 2) =
                    pkh(d[mi][j][2] + b0, d[mi][j][3] + b1);
            }
        }
    }
    __syncwarp();                             // warp-private V visible

    // ---- P·V -> Y accumulators; write Y -> YT ----
    {
        float yacc[2][4][4] = {};
#pragma unroll
        for (int mi = 0; mi < 2; ++mi) {
            const uint32_t rowa = (uint32_t)(r0 + mi * 16 + (lane & 15)) * RS +
                                  ((lane >> 4) << 4) + (uint32_t)nc0 * 2;
            uint32_t vb[8];
            ldsm4t(vb[0], vb[1], vb[2], vb[3], sb + XH + rowa);
            ldsm4t(vb[4], vb[5], vb[6], vb[7], sb + XH + rowa + 32);
            mma16816(yacc[mi][0], pa[mi][0], 0u, 0u, pa[mi][1], vb[0], vb[1]);
            mma16816(yacc[mi][1], pa[mi][0], 0u, 0u, pa[mi][1], vb[2], vb[3]);
            mma16816(yacc[mi][2], pa[mi][0], 0u, 0u, pa[mi][1], vb[4], vb[5]);
            mma16816(yacc[mi][3], pa[mi][0], 0u, 0u, pa[mi][1], vb[6], vb[7]);
        }
#pragma unroll
        for (int mi = 0; mi < 2; ++mi) {
            const int ra = r0 + mi * 16 + rq, rb = ra + 8;
#pragma unroll
            for (int nt = 0; nt < 4; ++nt) {
                const int col = nc0 + nt * 8 + c2;
                *(uint32_t*)(sm + YT + ra * RS + col * 2) = pkh(yacc[mi][nt][0], yacc[mi][nt][1]);
                *(uint32_t*)(sm + YT + rb * RS + col * 2) = pkh(yacc[mi][nt][2], yacc[mi][nt][3]);
            }
        }
    }
    CPA_WAIT0();                              // Wo complete
    __syncthreads();                          // (5) Y + Wo visible

    // ---- O GEMM (A=Y in YT, B=Wo in WB): out = Y·Wo^T + bo ----
    {
        load_a(sb + YT, r0, lane, af);
        float d[2][4][4] = {};
        warp_gemm_c(af, sb + WB, nc0, d, lane);
#pragma unroll
        for (int mi = 0; mi < 2; ++mi) {
            const int ra = r0 + mi * 16 + rq, rb = ra + 8;
            const float rma = rm_f[ra], rmb = rm_f[rb];
#pragma unroll
            for (int j = 0; j < 4; ++j) {
                const int col = colj[j];
                const float b0 = g_bias[3][col], b1 = g_bias[3][col + 1];
                float2 va, vb;
                va.x = (d[mi][j][0] + b0) * rma; va.y = (d[mi][j][1] + b1) * rma;
                vb.x = (d[mi][j][2] + b0) * rmb; vb.y = (d[mi][j][3] + b1) * rmb;
                *(float2*)(out + (tok0 + ra) * C + col) = va;
                *(float2*)(out + (tok0 + rb) * C + col) = vb;
            }
        }
    }
}

extern "C" void kernel_launch(void* const* d_in, const int* in_sizes, int n_in,
                              void* d_out, int out_size)
{
    const float* x    = (const float*)d_in[0];
    const int*   mask = (const int*)d_in[1];
    const float* Wq = (const float*)d_in[2];
    const float* bq = (const float*)d_in[3];
    const float* Wk = (const float*)d_in[4];
    const float* bk = (const float*)d_in[5];
    const float* Wv = (const float*)d_in[6];
    const float* bv = (const float*)d_in[7];
    const float* Wo = (const float*)d_in[8];
    const float* bo = (const float*)d_in[9];
    float* out = (float*)d_out;

    const int ntok = in_sizes[0] / laa::C;      // 262144
    const int nblk = ntok / laa::TOKS;          // 4096

    prep_split<<<32, 256>>>(Wq, bq, Wk, bk, Wv, bv, Wo, bo);

    cudaFuncSetAttribute(laa_mma_kernel,
                         cudaFuncAttributeMaxDynamicSharedMemorySize, laa::TOTAL);
    laa_mma_kernel<<<nblk, laa::NT, laa::TOTAL>>>(x, mask, out);
}